// round 16
// baseline (speedup 1.0000x reference)
#include <cuda_runtime.h>
#include <cuda_fp16.h>
#include <mma.h>
#include <math.h>
#include <stdint.h>

using namespace nvcuda;

// Problem constants
#define BATCH   4
#define SEQ     8192
#define DIM     768
#define CHUNK   64
#define M_ROWS  (BATCH * SEQ)       // 32768
#define DFF     (4 * DIM)           // 3072

// ---------------- scratch (static device globals) ----------------------------
__device__ __half g_h   [(size_t)M_ROWS * DIM];   // LN output (half)
__device__ __half g_mem [(size_t)M_ROWS * DIM];   // scan output (half)
__device__ __half g_ffn [(size_t)M_ROWS * DFF];   // ffn hidden (half)
__device__ __half g_wg  [(size_t)DIM * DIM];      // gate_W  half [K,N]
__device__ __half g_wv  [(size_t)DIM * DIM];      // value_W half
__device__ __half g_w1  [(size_t)DIM * DFF];      // ffn_W1  half
__device__ __half g_w2  [(size_t)DFF * DIM];      // ffn_W2  half

// ---------------- cp.async helpers -------------------------------------------
__device__ __forceinline__ uint32_t smem_u32(const void* p) {
    uint32_t a;
    asm("{ .reg .u64 t; cvta.to.shared.u64 t, %1; cvt.u32.u64 %0, t; }"
        : "=r"(a) : "l"(p));
    return a;
}
#define CP_ASYNC16(dst, src) \
    asm volatile("cp.async.cg.shared.global [%0], [%1], 16;" :: "r"(dst), "l"(src))
#define CP_COMMIT() asm volatile("cp.async.commit_group;" ::: "memory")
#define CP_WAIT(n)  asm volatile("cp.async.wait_group %0;" :: "n"(n) : "memory")

// ---------------- LayerNorm body: warp-per-row, pair-per-lane, vectorized -----
template <bool ADD_MEM>
__device__ __forceinline__ void ln_row(const float* __restrict__ xin,
                                       const __half* __restrict__ mem,
                                       const float* __restrict__ w,
                                       const float* __restrict__ b,
                                       float* __restrict__ xout,
                                       __half* __restrict__ hout,
                                       size_t row, int lane) {
    const size_t base = row * DIM;
    float2 vals[12];
    float s = 0.0f;
    #pragma unroll
    for (int i = 0; i < 12; i++) {
        int c = i * 64 + lane * 2;
        float2 xv = *reinterpret_cast<const float2*>(xin + base + c);
        if (ADD_MEM) {
            float2 mv = __half22float2(
                *reinterpret_cast<const __half2*>(mem + base + c));
            xv.x += mv.x;
            xv.y += mv.y;
            *reinterpret_cast<float2*>(xout + base + c) = xv;
        }
        vals[i] = xv;
        s += xv.x + xv.y;
    }
    #pragma unroll
    for (int o = 16; o > 0; o >>= 1) s += __shfl_xor_sync(0xffffffffu, s, o);
    const float mu = s * (1.0f / DIM);

    float sq = 0.0f;
    #pragma unroll
    for (int i = 0; i < 12; i++) {
        float dx = vals[i].x - mu;
        float dy = vals[i].y - mu;
        sq += dx * dx + dy * dy;
    }
    #pragma unroll
    for (int o = 16; o > 0; o >>= 1) sq += __shfl_xor_sync(0xffffffffu, sq, o);
    const float inv = rsqrtf(sq * (1.0f / DIM) + 1e-5f);

    #pragma unroll
    for (int i = 0; i < 12; i++) {
        int c = i * 64 + lane * 2;
        float2 wv = *reinterpret_cast<const float2*>(w + c);
        float2 bv = *reinterpret_cast<const float2*>(b + c);
        float h0 = (vals[i].x - mu) * inv * wv.x + bv.x;
        float h1 = (vals[i].y - mu) * inv * wv.y + bv.y;
        *reinterpret_cast<__half2*>(hout + base + c) = __floats2half2_rn(h0, h1);
    }
}

// ---------------- LN2 kernel: out = x + mem ; h = LN2(out) --------------------
__global__ __launch_bounds__(256)
void ln2_kernel(const float* __restrict__ xin, const __half* __restrict__ mem,
                const float* __restrict__ w, const float* __restrict__ b,
                float* __restrict__ xout, __half* __restrict__ hout) {
    const size_t row = (size_t)blockIdx.x * 8 + (threadIdx.x >> 5);
    ln_row<true>(xin, mem, w, b, xout, hout, row, threadIdx.x & 31);
}

// ---------------- fused LN1 + weight f2h (single launch) ----------------------
#define LN_BLOCKS (M_ROWS / 8)          // 4096
#define N_SQ  ((size_t)DIM * DIM)       // 589824
#define N_FF  ((size_t)DIM * DFF)       // 2359296
#define F2H_TOTAL4 ((2 * N_SQ + 2 * N_FF) / 4)             // 1474560
#define F2H_BLOCKS ((unsigned)((F2H_TOTAL4 + 255) / 256))  // 5760

__global__ __launch_bounds__(256)
void ln1_f2h_kernel(const float* __restrict__ x,
                    const float* __restrict__ w, const float* __restrict__ b,
                    __half* __restrict__ hout,
                    const float* __restrict__ s0, __half* __restrict__ d0,
                    const float* __restrict__ s1, __half* __restrict__ d1,
                    const float* __restrict__ s2, __half* __restrict__ d2,
                    const float* __restrict__ s3, __half* __restrict__ d3) {
    if (blockIdx.x < LN_BLOCKS) {
        const size_t row = (size_t)blockIdx.x * 8 + (threadIdx.x >> 5);
        ln_row<false>(x, nullptr, w, b, nullptr, hout, row, threadIdx.x & 31);
        return;
    }
    size_t i = ((size_t)(blockIdx.x - LN_BLOCKS) * 256 + threadIdx.x) * 4;
    const float* src; __half* dst;
    if      (i < N_SQ)                { src = s0; dst = d0; }
    else if (i < 2 * N_SQ)            { src = s1; dst = d1; i -= N_SQ; }
    else if (i < 2 * N_SQ + N_FF)     { src = s2; dst = d2; i -= 2 * N_SQ; }
    else if (i < 2 * N_SQ + 2 * N_FF) { src = s3; dst = d3; i -= 2 * N_SQ + N_FF; }
    else return;
    float4 v = *reinterpret_cast<const float4*>(src + i);
    *reinterpret_cast<__half2*>(dst + i)     = __floats2half2_rn(v.x, v.y);
    *reinterpret_cast<__half2*>(dst + i + 2) = __floats2half2_rn(v.z, v.w);
}

// =============== Fused gate+value GEMM + chunked scan (occupancy 2) ===========
#define GBM 128
#define GBN 64
#define GKT 64
#define GLDA 72
#define GLDB 72
#define GA_ST (GBM * GLDA)              // 9216 halfs
#define GB_ST (GKT * GLDB)              // 4608 halfs (per weight matrix)
#define GST_HALFS (GA_ST + 2 * GB_ST)   // 18432 halfs = 36864 B
#define GSMEM_BYTES (3 * GST_HALFS * 2) // 110592 B -> 2 CTAs/SM
#define GNT 256

__global__ __launch_bounds__(GNT, 2)
void gemm_gv_scan(const __half* __restrict__ A, const __half* __restrict__ Wg,
                  const __half* __restrict__ Wv,
                  const float* __restrict__ gate_b,
                  const float* __restrict__ value_b,
                  __half* __restrict__ mem_out) {
    extern __shared__ __align__(16) __half smem[];
    const int tid  = threadIdx.x;
    const int wid  = tid >> 5;      // 0..7
    const int lane = tid & 31;
    const int wm   = wid >> 2;      // 0..1 -> 64-row chunk (== CHUNK)
    const int wn   = wid & 3;       // 0..3 -> 16-col band

    const int bm = blockIdx.y * GBM;
    const int bn = blockIdx.x * GBN;
    const int K = DIM, N = DIM;
    const int kiters = K / GKT;     // 12

    const uint32_t smem_base = smem_u32(smem);

    auto load_stage = [&](int buf, int ki) {
        const int k0 = ki * GKT;
        const uint32_t stA  = smem_base + (uint32_t)buf * GST_HALFS * 2;
        const uint32_t stBg = stA + GA_ST * 2;
        const uint32_t stBv = stBg + GB_ST * 2;
        #pragma unroll
        for (int u = 0; u < 4; u++) {
            int f = tid + u * GNT;
            int row = f >> 3, cc = f & 7;
            CP_ASYNC16(stA + (uint32_t)(row * GLDA + cc * 8) * 2,
                       A + (size_t)(bm + row) * K + k0 + cc * 8);
        }
        #pragma unroll
        for (int u = 0; u < 2; u++) {
            int f = tid + u * GNT;
            int row = f >> 3, cc = f & 7;
            CP_ASYNC16(stBg + (uint32_t)(row * GLDB + cc * 8) * 2,
                       Wg + (size_t)(k0 + row) * N + bn + cc * 8);
            CP_ASYNC16(stBv + (uint32_t)(row * GLDB + cc * 8) * 2,
                       Wv + (size_t)(k0 + row) * N + bn + cc * 8);
        }
    };

    wmma::fragment<wmma::accumulator, 16, 16, 16, float> accg[4], accv[4];
    #pragma unroll
    for (int i = 0; i < 4; i++) {
        wmma::fill_fragment(accg[i], 0.0f);
        wmma::fill_fragment(accv[i], 0.0f);
    }

    #pragma unroll
    for (int s = 0; s < 2; s++) { load_stage(s, s); CP_COMMIT(); }

    for (int ki = 0; ki < kiters; ki++) {
        CP_WAIT(1);
        __syncthreads();

        int nxt = ki + 2;
        if (nxt < kiters) load_stage(nxt % 3, nxt);
        CP_COMMIT();

        const int buf = ki % 3;
        const __half* sA  = smem + (size_t)buf * GST_HALFS;
        const __half* sBg = sA + GA_ST;
        const __half* sBv = sBg + GB_ST;

        #pragma unroll
        for (int kk = 0; kk < GKT; kk += 16) {
            wmma::fragment<wmma::matrix_a, 16, 16, 16, __half, wmma::row_major> af[4];
            wmma::fragment<wmma::matrix_b, 16, 16, 16, __half, wmma::row_major> bgf, bvf;
            #pragma unroll
            for (int i = 0; i < 4; i++)
                wmma::load_matrix_sync(af[i], sA + (wm * 64 + i * 16) * GLDA + kk, GLDA);
            wmma::load_matrix_sync(bgf, sBg + kk * GLDB + wn * 16, GLDB);
            wmma::load_matrix_sync(bvf, sBv + kk * GLDB + wn * 16, GLDB);
            #pragma unroll
            for (int i = 0; i < 4; i++) {
                wmma::mma_sync(accg[i], af[i], bgf, accg[i]);
                wmma::mma_sync(accv[i], af[i], bvf, accv[i]);
            }
        }
    }

    // ---------------- epilogue: stage + per-column chunked scan ---------------
    __syncthreads();
    float* gt = reinterpret_cast<float*>(smem) + (size_t)wid * (2 * 64 * 20);
    float* vt = gt + 64 * 20;
    #pragma unroll
    for (int i = 0; i < 4; i++) {
        wmma::store_matrix_sync(gt + i * 16 * 20, accg[i], 20, wmma::mem_row_major);
        wmma::store_matrix_sync(vt + i * 16 * 20, accv[i], 20, wmma::mem_row_major);
    }
    __syncwarp();

    // Lanes 0..15 each own one feature column; warp rows == one CHUNK == 64.
    if (lane < 16) {
        const int gcol = bn + wn * 16 + lane;
        const float bg = gate_b[gcol];
        const float bv = value_b[gcol];
        const float* gp = gt + lane;
        const float* vp = vt + lane;
        __half* op = mem_out + (size_t)(bm + wm * 64) * DIM + gcol;
        float sg = 0.0f, sgv = 0.0f;
        #pragma unroll 8
        for (int r = 0; r < 64; r++) {
            float gval = gp[r * 20] + bg;
            gval = __fdividef(1.0f, 1.0f + __expf(-gval));
            float vval = vp[r * 20] + bv;
            sg  += gval;
            sgv += gval * vval;
            op[(size_t)r * DIM] = __float2half_rn(__fdividef(sgv, sg + 1e-6f));
        }
    }
}

// ---------------- FFN GEMM: BM=128, 256 threads, occupancy 2, NSTAGE=3 --------
#define BM 128
#define BN 128
#define KT 64
#define NSTAGE 3
#define LDA 72
#define LDB 136
#define A_ST (BM * LDA)                      // 9216 halfs
#define B_ST (KT * LDB)                      // 8704 halfs
#define ST_HALFS (A_ST + B_ST)               // 17920 halfs = 35840 B
#define SMEM_BYTES (NSTAGE * ST_HALFS * 2)   // 107520 B -> 2 CTAs/SM
#define NTHREADS 256

#define ACT_NONE 0
#define ACT_GELU 2

template <int ACT, bool ADD_OUT, bool OUT_HALF>
__global__ __launch_bounds__(NTHREADS, 2)
void gemm_fp16(const __half* __restrict__ A, const __half* __restrict__ B,
               const float* __restrict__ bias, float* __restrict__ Cf,
               __half* __restrict__ Ch, int N, int K) {
    extern __shared__ __align__(16) __half smem[];
    const int tid  = threadIdx.x;
    const int wid  = tid >> 5;      // 0..7
    const int lane = tid & 31;
    const int wm   = wid >> 2;      // 0..1 -> 64-row band
    const int wn   = wid & 3;       // 0..3 -> 32-col band

    const int bm = blockIdx.y * BM;
    const int bn = blockIdx.x * BN;
    const int kiters = K / KT;

    const uint32_t smem_base = smem_u32(smem);

    auto load_stage = [&](int buf, int ki) {
        const int k0 = ki * KT;
        const uint32_t stA = smem_base + (uint32_t)buf * ST_HALFS * 2;
        const uint32_t stB = stA + A_ST * 2;
        #pragma unroll
        for (int u = 0; u < 4; u++) {
            int f = tid + u * NTHREADS;
            int row = f >> 3, cc = f & 7;
            CP_ASYNC16(stA + (uint32_t)(row * LDA + cc * 8) * 2,
                       A + (size_t)(bm + row) * K + k0 + cc * 8);
        }
        #pragma unroll
        for (int u = 0; u < 4; u++) {
            int f = tid + u * NTHREADS;
            int row = f >> 4, cc = f & 15;
            CP_ASYNC16(stB + (uint32_t)(row * LDB + cc * 8) * 2,
                       B + (size_t)(k0 + row) * N + bn + cc * 8);
        }
    };

    wmma::fragment<wmma::accumulator, 16, 16, 16, float> acc[4][2];
    #pragma unroll
    for (int i = 0; i < 4; i++)
        #pragma unroll
        for (int j = 0; j < 2; j++)
            wmma::fill_fragment(acc[i][j], 0.0f);

    #pragma unroll
    for (int s = 0; s < NSTAGE - 1; s++) { load_stage(s, s); CP_COMMIT(); }

    for (int ki = 0; ki < kiters; ki++) {
        CP_WAIT(NSTAGE - 2);
        __syncthreads();

        int nxt = ki + NSTAGE - 1;
        if (nxt < kiters) load_stage(nxt % NSTAGE, nxt);
        CP_COMMIT();

        const int buf = ki % NSTAGE;
        const __half* sA = smem + (size_t)buf * ST_HALFS;
        const __half* sB = sA + A_ST;

        #pragma unroll
        for (int kk = 0; kk < KT; kk += 16) {
            wmma::fragment<wmma::matrix_a, 16, 16, 16, __half, wmma::row_major> af[4];
            wmma::fragment<wmma::matrix_b, 16, 16, 16, __half, wmma::row_major> bf[2];
            #pragma unroll
            for (int i = 0; i < 4; i++)
                wmma::load_matrix_sync(af[i], sA + (wm * 64 + i * 16) * LDA + kk, LDA);
            #pragma unroll
            for (int j = 0; j < 2; j++)
                wmma::load_matrix_sync(bf[j], sB + kk * LDB + wn * 32 + j * 16, LDB);
            #pragma unroll
            for (int i = 0; i < 4; i++)
                #pragma unroll
                for (int j = 0; j < 2; j++)
                    wmma::mma_sync(acc[i][j], af[i], bf[j], acc[i][j]);
        }
    }

    // ---------------- epilogue: per-warp smem staging, fused bias/act ---------
    __syncthreads();
    float* stile = reinterpret_cast<float*>(smem) + (size_t)wid * 32 * 36;

    #pragma unroll
    for (int h = 0; h < 2; h++) {          // two 32-row halves of the 64x32 warp tile
        #pragma unroll
        for (int j = 0; j < 2; j++)
            wmma::store_matrix_sync(stile + j * 16,
                                    acc[h * 2 + 0][j], 36, wmma::mem_row_major);
        #pragma unroll
        for (int j = 0; j < 2; j++)
            wmma::store_matrix_sync(stile + 16 * 36 + j * 16,
                                    acc[h * 2 + 1][j], 36, wmma::mem_row_major);
        __syncwarp();
        if (OUT_HALF) {
            #pragma unroll
            for (int it = 0; it < 16; it++) {
                int idx = it * 32 + lane;
                int row = idx >> 4;
                int cp  = idx & 15;          // column pair
                int grow = bm + wm * 64 + h * 32 + row;
                int gcol = bn + wn * 32 + cp * 2;
                float v0 = stile[row * 36 + cp * 2 + 0] + bias[gcol + 0];
                float v1 = stile[row * 36 + cp * 2 + 1] + bias[gcol + 1];
                if (ACT == ACT_GELU) {
                    v0 = v0 * normcdff(v0);   // == 0.5*v*(1+erf(v/sqrt2)), exact gelu
                    v1 = v1 * normcdff(v1);
                }
                *reinterpret_cast<__half2*>(Ch + (size_t)grow * N + gcol) =
                    __floats2half2_rn(v0, v1);
            }
        } else {
            // float2-vectorized RMW epilogue (residual add path)
            #pragma unroll
            for (int it = 0; it < 16; it++) {
                int idx = it * 32 + lane;
                int row = idx >> 4;
                int cp  = idx & 15;          // column pair
                int grow = bm + wm * 64 + h * 32 + row;
                int gcol = bn + wn * 32 + cp * 2;
                float2 bv = *reinterpret_cast<const float2*>(bias + gcol);
                float v0 = stile[row * 36 + cp * 2 + 0] + bv.x;
                float v1 = stile[row * 36 + cp * 2 + 1] + bv.y;
                if (ACT == ACT_GELU) {
                    v0 = v0 * normcdff(v0);
                    v1 = v1 * normcdff(v1);
                }
                float2* cptr = reinterpret_cast<float2*>(Cf + (size_t)grow * N + gcol);
                if (ADD_OUT) {
                    float2 prev = *cptr;
                    v0 += prev.x;
                    v1 += prev.y;
                }
                *cptr = make_float2(v0, v1);
            }
        }
        __syncwarp();
    }
}

// ---------------- launcher ----------------------------------------------------
extern "C" void kernel_launch(void* const* d_in, const int* in_sizes, int n_in,
                              void* d_out, int out_size) {
    const float* x       = (const float*)d_in[0];
    const float* n1w     = (const float*)d_in[1];
    const float* n1b     = (const float*)d_in[2];
    const float* n2w     = (const float*)d_in[3];
    const float* n2b     = (const float*)d_in[4];
    const float* gate_W  = (const float*)d_in[5];
    const float* gate_b  = (const float*)d_in[6];
    const float* value_W = (const float*)d_in[7];
    const float* value_b = (const float*)d_in[8];
    const float* ffn_W1  = (const float*)d_in[9];
    const float* ffn_b1  = (const float*)d_in[10];
    const float* ffn_W2  = (const float*)d_in[11];
    const float* ffn_b2  = (const float*)d_in[12];
    float* out = (float*)d_out;

    __half *h, *mem, *ffn, *wg, *wv, *w1, *w2;
    cudaGetSymbolAddress((void**)&h,   g_h);
    cudaGetSymbolAddress((void**)&mem, g_mem);
    cudaGetSymbolAddress((void**)&ffn, g_ffn);
    cudaGetSymbolAddress((void**)&wg,  g_wg);
    cudaGetSymbolAddress((void**)&wv,  g_wv);
    cudaGetSymbolAddress((void**)&w1,  g_w1);
    cudaGetSymbolAddress((void**)&w2,  g_w2);

    cudaFuncSetAttribute(gemm_gv_scan,
                         cudaFuncAttributeMaxDynamicSharedMemorySize, GSMEM_BYTES);
    cudaFuncSetAttribute(gemm_fp16<ACT_GELU, false, true>,
                         cudaFuncAttributeMaxDynamicSharedMemorySize, SMEM_BYTES);
    cudaFuncSetAttribute(gemm_fp16<ACT_NONE, true,  false>,
                         cudaFuncAttributeMaxDynamicSharedMemorySize, SMEM_BYTES);

    // 1. fused: h = LN1(x)  +  all-weights f32->f16 (single launch)
    ln1_f2h_kernel<<<LN_BLOCKS + F2H_BLOCKS, 256>>>(
        x, n1w, n1b, h,
        gate_W, wg, value_W, wv, ffn_W1, w1, ffn_W2, w2);

    // 2+3+4 fused: mem(half) = chunked_scan(sigmoid(h@Wg+bg), h@Wv+bv)
    gemm_gv_scan<<<dim3(DIM / GBN, M_ROWS / GBM), GNT, GSMEM_BYTES>>>(
        h, wg, wv, gate_b, value_b, mem);

    // 5. out = x + mem ; h = LN2(out) (half)  -- streaming, coalesced, vectorized
    ln2_kernel<<<M_ROWS / 8, 256>>>(x, mem, n2w, n2b, out, h);

    // 6. ffn = gelu(h @ W1 + b1)            (half out)
    gemm_fp16<ACT_GELU, false, true><<<dim3(DFF / BN, M_ROWS / BM), NTHREADS, SMEM_BYTES>>>(
        h, w1, ffn_b1, nullptr, ffn, DFF, DIM);
    // 7. out += ffn @ W2 + b2               (f32 out, residual, float2 RMW)
    gemm_fp16<ACT_NONE, true, false><<<dim3(DIM / BN, M_ROWS / BM), NTHREADS, SMEM_BYTES>>>(
        ffn, w2, ffn_b2, out, nullptr, DIM, DFF);
}

// round 17
// speedup vs baseline: 1.0643x; 1.0643x over previous
#include <cuda_runtime.h>
#include <cuda_fp16.h>
#include <mma.h>
#include <math.h>
#include <stdint.h>

using namespace nvcuda;

// Problem constants
#define BATCH   4
#define SEQ     8192
#define DIM     768
#define CHUNK   64
#define M_ROWS  (BATCH * SEQ)       // 32768
#define DFF     (4 * DIM)           // 3072

// ---------------- scratch (static device globals) ----------------------------
__device__ __half g_h   [(size_t)M_ROWS * DIM];   // LN output (half)
__device__ __half g_mem [(size_t)M_ROWS * DIM];   // scan output (half)
__device__ __half g_ffn [(size_t)M_ROWS * DFF];   // ffn hidden (half)
__device__ __half g_wg  [(size_t)DIM * DIM];      // gate_W  half [K,N]
__device__ __half g_wv  [(size_t)DIM * DIM];      // value_W half
__device__ __half g_w1  [(size_t)DIM * DFF];      // ffn_W1  half
__device__ __half g_w2  [(size_t)DFF * DIM];      // ffn_W2  half

// ---------------- cp.async helpers -------------------------------------------
__device__ __forceinline__ uint32_t smem_u32(const void* p) {
    uint32_t a;
    asm("{ .reg .u64 t; cvta.to.shared.u64 t, %1; cvt.u32.u64 %0, t; }"
        : "=r"(a) : "l"(p));
    return a;
}
#define CP_ASYNC16(dst, src) \
    asm volatile("cp.async.cg.shared.global [%0], [%1], 16;" :: "r"(dst), "l"(src))
#define CP_COMMIT() asm volatile("cp.async.commit_group;" ::: "memory")
#define CP_WAIT(n)  asm volatile("cp.async.wait_group %0;" :: "n"(n) : "memory")

// exact gelu (erff form — verified fast on this part; normcdff regressed R16)
__device__ __forceinline__ float gelu_exact(float v) {
    return 0.5f * v * (1.0f + erff(v * 0.70710678118654752f));
}

// ---------------- LayerNorm body: warp-per-row, pair-per-lane, vectorized -----
template <bool ADD_MEM>
__device__ __forceinline__ void ln_row(const float* __restrict__ xin,
                                       const __half* __restrict__ mem,
                                       const float* __restrict__ w,
                                       const float* __restrict__ b,
                                       float* __restrict__ xout,
                                       __half* __restrict__ hout,
                                       size_t row, int lane) {
    const size_t base = row * DIM;
    float2 vals[12];
    float s = 0.0f;
    #pragma unroll
    for (int i = 0; i < 12; i++) {
        int c = i * 64 + lane * 2;
        float2 xv = *reinterpret_cast<const float2*>(xin + base + c);
        if (ADD_MEM) {
            float2 mv = __half22float2(
                *reinterpret_cast<const __half2*>(mem + base + c));
            xv.x += mv.x;
            xv.y += mv.y;
            *reinterpret_cast<float2*>(xout + base + c) = xv;
        }
        vals[i] = xv;
        s += xv.x + xv.y;
    }
    #pragma unroll
    for (int o = 16; o > 0; o >>= 1) s += __shfl_xor_sync(0xffffffffu, s, o);
    const float mu = s * (1.0f / DIM);

    float sq = 0.0f;
    #pragma unroll
    for (int i = 0; i < 12; i++) {
        float dx = vals[i].x - mu;
        float dy = vals[i].y - mu;
        sq += dx * dx + dy * dy;
    }
    #pragma unroll
    for (int o = 16; o > 0; o >>= 1) sq += __shfl_xor_sync(0xffffffffu, sq, o);
    const float inv = rsqrtf(sq * (1.0f / DIM) + 1e-5f);

    #pragma unroll
    for (int i = 0; i < 12; i++) {
        int c = i * 64 + lane * 2;
        float2 wv = *reinterpret_cast<const float2*>(w + c);
        float2 bv = *reinterpret_cast<const float2*>(b + c);
        float h0 = (vals[i].x - mu) * inv * wv.x + bv.x;
        float h1 = (vals[i].y - mu) * inv * wv.y + bv.y;
        *reinterpret_cast<__half2*>(hout + base + c) = __floats2half2_rn(h0, h1);
    }
}

// ---------------- LN2 kernel: out = x + mem ; h = LN2(out) --------------------
__global__ __launch_bounds__(256)
void ln2_kernel(const float* __restrict__ xin, const __half* __restrict__ mem,
                const float* __restrict__ w, const float* __restrict__ b,
                float* __restrict__ xout, __half* __restrict__ hout) {
    const size_t row = (size_t)blockIdx.x * 8 + (threadIdx.x >> 5);
    ln_row<true>(xin, mem, w, b, xout, hout, row, threadIdx.x & 31);
}

// ---------------- fused LN1 + weight f2h (single launch) ----------------------
#define LN_BLOCKS (M_ROWS / 8)          // 4096
#define N_SQ  ((size_t)DIM * DIM)       // 589824
#define N_FF  ((size_t)DIM * DFF)       // 2359296
#define F2H_TOTAL4 ((2 * N_SQ + 2 * N_FF) / 4)             // 1474560
#define F2H_BLOCKS ((unsigned)((F2H_TOTAL4 + 255) / 256))  // 5760

__global__ __launch_bounds__(256)
void ln1_f2h_kernel(const float* __restrict__ x,
                    const float* __restrict__ w, const float* __restrict__ b,
                    __half* __restrict__ hout,
                    const float* __restrict__ s0, __half* __restrict__ d0,
                    const float* __restrict__ s1, __half* __restrict__ d1,
                    const float* __restrict__ s2, __half* __restrict__ d2,
                    const float* __restrict__ s3, __half* __restrict__ d3) {
    if (blockIdx.x < LN_BLOCKS) {
        const size_t row = (size_t)blockIdx.x * 8 + (threadIdx.x >> 5);
        ln_row<false>(x, nullptr, w, b, nullptr, hout, row, threadIdx.x & 31);
        return;
    }
    size_t i = ((size_t)(blockIdx.x - LN_BLOCKS) * 256 + threadIdx.x) * 4;
    const float* src; __half* dst;
    if      (i < N_SQ)                { src = s0; dst = d0; }
    else if (i < 2 * N_SQ)            { src = s1; dst = d1; i -= N_SQ; }
    else if (i < 2 * N_SQ + N_FF)     { src = s2; dst = d2; i -= 2 * N_SQ; }
    else if (i < 2 * N_SQ + 2 * N_FF) { src = s3; dst = d3; i -= 2 * N_SQ + N_FF; }
    else return;
    float4 v = *reinterpret_cast<const float4*>(src + i);
    *reinterpret_cast<__half2*>(dst + i)     = __floats2half2_rn(v.x, v.y);
    *reinterpret_cast<__half2*>(dst + i + 2) = __floats2half2_rn(v.z, v.w);
}

// =============== Fused gate+value GEMM + chunked scan (occupancy 2) ===========
#define GBM 128
#define GBN 64
#define GKT 64
#define GLDA 72
#define GLDB 72
#define GA_ST (GBM * GLDA)              // 9216 halfs
#define GB_ST (GKT * GLDB)              // 4608 halfs (per weight matrix)
#define GST_HALFS (GA_ST + 2 * GB_ST)   // 18432 halfs = 36864 B
#define GSMEM_BYTES (3 * GST_HALFS * 2) // 110592 B -> 2 CTAs/SM
#define GNT 256

__global__ __launch_bounds__(GNT, 2)
void gemm_gv_scan(const __half* __restrict__ A, const __half* __restrict__ Wg,
                  const __half* __restrict__ Wv,
                  const float* __restrict__ gate_b,
                  const float* __restrict__ value_b,
                  __half* __restrict__ mem_out) {
    extern __shared__ __align__(16) __half smem[];
    const int tid  = threadIdx.x;
    const int wid  = tid >> 5;      // 0..7
    const int lane = tid & 31;
    const int wm   = wid >> 2;      // 0..1 -> 64-row chunk (== CHUNK)
    const int wn   = wid & 3;       // 0..3 -> 16-col band

    const int bm = blockIdx.y * GBM;
    const int bn = blockIdx.x * GBN;
    const int K = DIM, N = DIM;
    const int kiters = K / GKT;     // 12

    const uint32_t smem_base = smem_u32(smem);

    auto load_stage = [&](int buf, int ki) {
        const int k0 = ki * GKT;
        const uint32_t stA  = smem_base + (uint32_t)buf * GST_HALFS * 2;
        const uint32_t stBg = stA + GA_ST * 2;
        const uint32_t stBv = stBg + GB_ST * 2;
        #pragma unroll
        for (int u = 0; u < 4; u++) {
            int f = tid + u * GNT;
            int row = f >> 3, cc = f & 7;
            CP_ASYNC16(stA + (uint32_t)(row * GLDA + cc * 8) * 2,
                       A + (size_t)(bm + row) * K + k0 + cc * 8);
        }
        #pragma unroll
        for (int u = 0; u < 2; u++) {
            int f = tid + u * GNT;
            int row = f >> 3, cc = f & 7;
            CP_ASYNC16(stBg + (uint32_t)(row * GLDB + cc * 8) * 2,
                       Wg + (size_t)(k0 + row) * N + bn + cc * 8);
            CP_ASYNC16(stBv + (uint32_t)(row * GLDB + cc * 8) * 2,
                       Wv + (size_t)(k0 + row) * N + bn + cc * 8);
        }
    };

    wmma::fragment<wmma::accumulator, 16, 16, 16, float> accg[4], accv[4];
    #pragma unroll
    for (int i = 0; i < 4; i++) {
        wmma::fill_fragment(accg[i], 0.0f);
        wmma::fill_fragment(accv[i], 0.0f);
    }

    #pragma unroll
    for (int s = 0; s < 2; s++) { load_stage(s, s); CP_COMMIT(); }

    for (int ki = 0; ki < kiters; ki++) {
        CP_WAIT(1);
        __syncthreads();

        int nxt = ki + 2;
        if (nxt < kiters) load_stage(nxt % 3, nxt);
        CP_COMMIT();

        const int buf = ki % 3;
        const __half* sA  = smem + (size_t)buf * GST_HALFS;
        const __half* sBg = sA + GA_ST;
        const __half* sBv = sBg + GB_ST;

        #pragma unroll
        for (int kk = 0; kk < GKT; kk += 16) {
            wmma::fragment<wmma::matrix_a, 16, 16, 16, __half, wmma::row_major> af[4];
            wmma::fragment<wmma::matrix_b, 16, 16, 16, __half, wmma::row_major> bgf, bvf;
            #pragma unroll
            for (int i = 0; i < 4; i++)
                wmma::load_matrix_sync(af[i], sA + (wm * 64 + i * 16) * GLDA + kk, GLDA);
            wmma::load_matrix_sync(bgf, sBg + kk * GLDB + wn * 16, GLDB);
            wmma::load_matrix_sync(bvf, sBv + kk * GLDB + wn * 16, GLDB);
            #pragma unroll
            for (int i = 0; i < 4; i++) {
                wmma::mma_sync(accg[i], af[i], bgf, accg[i]);
                wmma::mma_sync(accv[i], af[i], bvf, accv[i]);
            }
        }
    }

    // ---------------- epilogue: stage + per-column chunked scan ---------------
    __syncthreads();
    float* gt = reinterpret_cast<float*>(smem) + (size_t)wid * (2 * 64 * 20);
    float* vt = gt + 64 * 20;
    #pragma unroll
    for (int i = 0; i < 4; i++) {
        wmma::store_matrix_sync(gt + i * 16 * 20, accg[i], 20, wmma::mem_row_major);
        wmma::store_matrix_sync(vt + i * 16 * 20, accv[i], 20, wmma::mem_row_major);
    }
    __syncwarp();

    // Lanes 0..15 each own one feature column; warp rows == one CHUNK == 64.
    if (lane < 16) {
        const int gcol = bn + wn * 16 + lane;
        const float bg = gate_b[gcol];
        const float bv = value_b[gcol];
        const float* gp = gt + lane;
        const float* vp = vt + lane;
        __half* op = mem_out + (size_t)(bm + wm * 64) * DIM + gcol;
        float sg = 0.0f, sgv = 0.0f;
        #pragma unroll 8
        for (int r = 0; r < 64; r++) {
            float gval = gp[r * 20] + bg;
            gval = __fdividef(1.0f, 1.0f + __expf(-gval));
            float vval = vp[r * 20] + bv;
            sg  += gval;
            sgv += gval * vval;
            op[(size_t)r * DIM] = __float2half_rn(__fdividef(sgv, sg + 1e-6f));
        }
    }
}

// ---------------- FFN GEMM: BM=128, 256 threads, occupancy 2, NSTAGE=3 --------
#define BM 128
#define BN 128
#define KT 64
#define NSTAGE 3
#define LDA 72
#define LDB 136
#define A_ST (BM * LDA)                      // 9216 halfs
#define B_ST (KT * LDB)                      // 8704 halfs
#define ST_HALFS (A_ST + B_ST)               // 17920 halfs = 35840 B
#define SMEM_BYTES (NSTAGE * ST_HALFS * 2)   // 107520 B -> 2 CTAs/SM
#define NTHREADS 256

#define ACT_NONE 0
#define ACT_GELU 2

template <int ACT, bool ADD_OUT, bool OUT_HALF>
__global__ __launch_bounds__(NTHREADS, 2)
void gemm_fp16(const __half* __restrict__ A, const __half* __restrict__ B,
               const float* __restrict__ bias, float* __restrict__ Cf,
               __half* __restrict__ Ch, int N, int K) {
    extern __shared__ __align__(16) __half smem[];
    const int tid  = threadIdx.x;
    const int wid  = tid >> 5;      // 0..7
    const int lane = tid & 31;
    const int wm   = wid >> 2;      // 0..1 -> 64-row band
    const int wn   = wid & 3;       // 0..3 -> 32-col band

    const int bm = blockIdx.y * BM;
    const int bn = blockIdx.x * BN;
    const int kiters = K / KT;

    const uint32_t smem_base = smem_u32(smem);

    auto load_stage = [&](int buf, int ki) {
        const int k0 = ki * KT;
        const uint32_t stA = smem_base + (uint32_t)buf * ST_HALFS * 2;
        const uint32_t stB = stA + A_ST * 2;
        #pragma unroll
        for (int u = 0; u < 4; u++) {
            int f = tid + u * NTHREADS;
            int row = f >> 3, cc = f & 7;
            CP_ASYNC16(stA + (uint32_t)(row * LDA + cc * 8) * 2,
                       A + (size_t)(bm + row) * K + k0 + cc * 8);
        }
        #pragma unroll
        for (int u = 0; u < 4; u++) {
            int f = tid + u * NTHREADS;
            int row = f >> 4, cc = f & 15;
            CP_ASYNC16(stB + (uint32_t)(row * LDB + cc * 8) * 2,
                       B + (size_t)(k0 + row) * N + bn + cc * 8);
        }
    };

    wmma::fragment<wmma::accumulator, 16, 16, 16, float> acc[4][2];
    #pragma unroll
    for (int i = 0; i < 4; i++)
        #pragma unroll
        for (int j = 0; j < 2; j++)
            wmma::fill_fragment(acc[i][j], 0.0f);

    #pragma unroll
    for (int s = 0; s < NSTAGE - 1; s++) { load_stage(s, s); CP_COMMIT(); }

    for (int ki = 0; ki < kiters; ki++) {
        CP_WAIT(NSTAGE - 2);
        __syncthreads();

        int nxt = ki + NSTAGE - 1;
        if (nxt < kiters) load_stage(nxt % NSTAGE, nxt);
        CP_COMMIT();

        const int buf = ki % NSTAGE;
        const __half* sA = smem + (size_t)buf * ST_HALFS;
        const __half* sB = sA + A_ST;

        #pragma unroll
        for (int kk = 0; kk < KT; kk += 16) {
            wmma::fragment<wmma::matrix_a, 16, 16, 16, __half, wmma::row_major> af[4];
            wmma::fragment<wmma::matrix_b, 16, 16, 16, __half, wmma::row_major> bf[2];
            #pragma unroll
            for (int i = 0; i < 4; i++)
                wmma::load_matrix_sync(af[i], sA + (wm * 64 + i * 16) * LDA + kk, LDA);
            #pragma unroll
            for (int j = 0; j < 2; j++)
                wmma::load_matrix_sync(bf[j], sB + kk * LDB + wn * 32 + j * 16, LDB);
            #pragma unroll
            for (int i = 0; i < 4; i++)
                #pragma unroll
                for (int j = 0; j < 2; j++)
                    wmma::mma_sync(acc[i][j], af[i], bf[j], acc[i][j]);
        }
    }

    // ---------------- epilogue: per-warp smem staging, fused bias/act ---------
    __syncthreads();
    float* stile = reinterpret_cast<float*>(smem) + (size_t)wid * 32 * 36;

    #pragma unroll
    for (int h = 0; h < 2; h++) {          // two 32-row halves of the 64x32 warp tile
        #pragma unroll
        for (int j = 0; j < 2; j++)
            wmma::store_matrix_sync(stile + j * 16,
                                    acc[h * 2 + 0][j], 36, wmma::mem_row_major);
        #pragma unroll
        for (int j = 0; j < 2; j++)
            wmma::store_matrix_sync(stile + 16 * 36 + j * 16,
                                    acc[h * 2 + 1][j], 36, wmma::mem_row_major);
        __syncwarp();
        if (OUT_HALF) {
            #pragma unroll
            for (int it = 0; it < 16; it++) {
                int idx = it * 32 + lane;
                int row = idx >> 4;
                int cp  = idx & 15;          // column pair
                int grow = bm + wm * 64 + h * 32 + row;
                int gcol = bn + wn * 32 + cp * 2;
                float v0 = stile[row * 36 + cp * 2 + 0] + bias[gcol + 0];
                float v1 = stile[row * 36 + cp * 2 + 1] + bias[gcol + 1];
                if (ACT == ACT_GELU) {
                    v0 = gelu_exact(v0);
                    v1 = gelu_exact(v1);
                }
                *reinterpret_cast<__half2*>(Ch + (size_t)grow * N + gcol) =
                    __floats2half2_rn(v0, v1);
            }
        } else {
            // float2-vectorized RMW epilogue (residual add path)
            #pragma unroll
            for (int it = 0; it < 16; it++) {
                int idx = it * 32 + lane;
                int row = idx >> 4;
                int cp  = idx & 15;          // column pair
                int grow = bm + wm * 64 + h * 32 + row;
                int gcol = bn + wn * 32 + cp * 2;
                float2 bv = *reinterpret_cast<const float2*>(bias + gcol);
                float v0 = stile[row * 36 + cp * 2 + 0] + bv.x;
                float v1 = stile[row * 36 + cp * 2 + 1] + bv.y;
                if (ACT == ACT_GELU) {
                    v0 = gelu_exact(v0);
                    v1 = gelu_exact(v1);
                }
                float2* cptr = reinterpret_cast<float2*>(Cf + (size_t)grow * N + gcol);
                if (ADD_OUT) {
                    float2 prev = *cptr;
                    v0 += prev.x;
                    v1 += prev.y;
                }
                *cptr = make_float2(v0, v1);
            }
        }
        __syncwarp();
    }
}

// ---------------- launcher ----------------------------------------------------
extern "C" void kernel_launch(void* const* d_in, const int* in_sizes, int n_in,
                              void* d_out, int out_size) {
    const float* x       = (const float*)d_in[0];
    const float* n1w     = (const float*)d_in[1];
    const float* n1b     = (const float*)d_in[2];
    const float* n2w     = (const float*)d_in[3];
    const float* n2b     = (const float*)d_in[4];
    const float* gate_W  = (const float*)d_in[5];
    const float* gate_b  = (const float*)d_in[6];
    const float* value_W = (const float*)d_in[7];
    const float* value_b = (const float*)d_in[8];
    const float* ffn_W1  = (const float*)d_in[9];
    const float* ffn_b1  = (const float*)d_in[10];
    const float* ffn_W2  = (const float*)d_in[11];
    const float* ffn_b2  = (const float*)d_in[12];
    float* out = (float*)d_out;

    __half *h, *mem, *ffn, *wg, *wv, *w1, *w2;
    cudaGetSymbolAddress((void**)&h,   g_h);
    cudaGetSymbolAddress((void**)&mem, g_mem);
    cudaGetSymbolAddress((void**)&ffn, g_ffn);
    cudaGetSymbolAddress((void**)&wg,  g_wg);
    cudaGetSymbolAddress((void**)&wv,  g_wv);
    cudaGetSymbolAddress((void**)&w1,  g_w1);
    cudaGetSymbolAddress((void**)&w2,  g_w2);

    cudaFuncSetAttribute(gemm_gv_scan,
                         cudaFuncAttributeMaxDynamicSharedMemorySize, GSMEM_BYTES);
    cudaFuncSetAttribute(gemm_fp16<ACT_GELU, false, true>,
                         cudaFuncAttributeMaxDynamicSharedMemorySize, SMEM_BYTES);
    cudaFuncSetAttribute(gemm_fp16<ACT_NONE, true,  false>,
                         cudaFuncAttributeMaxDynamicSharedMemorySize, SMEM_BYTES);

    // 1. fused: h = LN1(x)  +  all-weights f32->f16 (single launch)
    ln1_f2h_kernel<<<LN_BLOCKS + F2H_BLOCKS, 256>>>(
        x, n1w, n1b, h,
        gate_W, wg, value_W, wv, ffn_W1, w1, ffn_W2, w2);

    // 2+3+4 fused: mem(half) = chunked_scan(sigmoid(h@Wg+bg), h@Wv+bv)
    gemm_gv_scan<<<dim3(DIM / GBN, M_ROWS / GBM), GNT, GSMEM_BYTES>>>(
        h, wg, wv, gate_b, value_b, mem);

    // 5. out = x + mem ; h = LN2(out) (half)  -- streaming, coalesced, vectorized
    ln2_kernel<<<M_ROWS / 8, 256>>>(x, mem, n2w, n2b, out, h);

    // 6. ffn = gelu(h @ W1 + b1)            (half out)
    gemm_fp16<ACT_GELU, false, true><<<dim3(DFF / BN, M_ROWS / BM), NTHREADS, SMEM_BYTES>>>(
        h, w1, ffn_b1, nullptr, ffn, DFF, DIM);
    // 7. out += ffn @ W2 + b2               (f32 out, residual, float2 RMW)
    gemm_fp16<ACT_NONE, true, false><<<dim3(DIM / BN, M_ROWS / BM), NTHREADS, SMEM_BYTES>>>(
        ffn, w2, ffn_b2, out, nullptr, DIM, DFF);
}